// round 16
// baseline (speedup 1.0000x reference)
#include <cuda_runtime.h>
#include <cuda_fp16.h>
#include <cstdint>

// ─────────────────────────────────────────────────────────────────────────────
// Dims
// ─────────────────────────────────────────────────────────────────────────────
#define BB 2
#define SS 2048
#define DD 768
#define HH 12
#define DK 64
#define BH 24           // BB*HH
#define MM 4096         // BB*SS

#define QSCALE 0.18033688f   // 0.125 * log2(e)

// ─────────────────────────────────────────────────────────────────────────────
// Scratch (static device globals — no allocation). Single fp16 plane each.
// ─────────────────────────────────────────────────────────────────────────────
__device__ __half g_xq[MM * DD], g_xk[MM * DD], g_xv[MM * DD];
__device__ __half g_wq[DD * DD], g_wk[DD * DD], g_wv[DD * DD], g_wo[DD * DD];
__device__ __half g_Q[BH * SS * DK];     // pre-scaled by 0.125*log2e
__device__ __half g_K[BH * SS * DK];
__device__ __half g_Vt[BH * SS * DK];    // [bh, dk, s]
__device__ __half g_O[MM * DD];          // merged heads [B*S, D]

// ─────────────────────────────────────────────────────────────────────────────
// PTX helpers (baseline ISA only — harness targets sm_103 non-'a', no tcgen05)
// ─────────────────────────────────────────────────────────────────────────────
__device__ __forceinline__ uint32_t smem_u32(const void* p) {
    uint32_t a;
    asm("{ .reg .u64 t; cvta.to.shared.u64 t, %1; cvt.u32.u64 %0, t; }"
        : "=r"(a) : "l"(p));
    return a;
}

__device__ __forceinline__ void cp_async16(uint32_t saddr, const void* gaddr) {
    asm volatile("cp.async.ca.shared.global [%0], [%1], 16;"
                 :: "r"(saddr), "l"(gaddr));
}
__device__ __forceinline__ void cp_commit() {
    asm volatile("cp.async.commit_group;");
}
__device__ __forceinline__ void cp_wait_all() {
    asm volatile("cp.async.wait_group 0;");
}
__device__ __forceinline__ void cp_wait_1() {
    asm volatile("cp.async.wait_group 1;");
}

__device__ __forceinline__ void ldm_x4(uint32_t addr, uint32_t* r) {
    asm volatile("ldmatrix.sync.aligned.m8n8.x4.shared.b16 {%0,%1,%2,%3}, [%4];"
                 : "=r"(r[0]), "=r"(r[1]), "=r"(r[2]), "=r"(r[3]) : "r"(addr));
}

// fp16 in, fp32 accumulate
__device__ __forceinline__ void mma16816(float* c, const uint32_t* a, const uint32_t* b) {
    asm volatile(
        "mma.sync.aligned.m16n8k16.row.col.f32.f16.f16.f32 "
        "{%0,%1,%2,%3}, {%4,%5,%6,%7}, {%8,%9}, {%0,%1,%2,%3};"
        : "+f"(c[0]), "+f"(c[1]), "+f"(c[2]), "+f"(c[3])
        : "r"(a[0]), "r"(a[1]), "r"(a[2]), "r"(a[3]), "r"(b[0]), "r"(b[1]));
}

__device__ __forceinline__ uint32_t pack_h2(float a, float b) {
    __half2 t = __floats2half2_rn(a, b);   // a in low half
    return *(uint32_t*)&t;
}

__device__ __forceinline__ float ex2(float x) {
    float y;
    asm("ex2.approx.f32 %0, %1;" : "=f"(y) : "f"(x));
    return y;
}

// half2 exp2 — one MUFU for two values
__device__ __forceinline__ uint32_t h2ex2(uint32_t x) {
    uint32_t y;
    asm("ex2.approx.f16x2 %0, %1;" : "=r"(y) : "r"(x));
    return y;
}

// ─────────────────────────────────────────────────────────────────────────────
// GEMM mainloop A: BM=128 (measured best for proj_qkv, ~2 perfect waves).
// BN=128, BK=64, 256 thr / 8 warps (2x4), warp tile 64x32, acc[4][4][4].
// ─────────────────────────────────────────────────────────────────────────────
#define GEMM_LDSB   144                  // 64 fp16 = 128B + 16B pad
#define GA_ATILE    (128 * GEMM_LDSB)    // 18432
#define GA_STAGE    (2 * GA_ATILE)       // 36864
#define GA_SMEM     (3 * GA_STAGE)       // 110592

__device__ __forceinline__ void gemm_mainloop_128(
    const __half* __restrict__ pA, int lda,
    const __half* __restrict__ pB, int ldb,
    int K, uint32_t sb, int tid, float acc[4][4][4])
{
    const int w    = tid >> 5;
    const int lane = tid & 31;
    const int wm0 = (w & 1) * 64;
    const int wn0 = (w >> 1) * 32;

    auto load_stage = [&](int st, int k0) {
        const uint32_t s0 = sb + st * GA_STAGE;
        for (int c = tid; c < 1024; c += 256) {     // 128 rows x 8 chunks, A and B
            const int r = c >> 3, kc = c & 7;
            cp_async16(s0 + r * GEMM_LDSB + kc * 16, pA + (size_t)r * lda + k0 + kc * 8);
            cp_async16(s0 + GA_ATILE + r * GEMM_LDSB + kc * 16,
                       pB + (size_t)r * ldb + k0 + kc * 8);
        }
        cp_commit();
    };

#pragma unroll
    for (int i = 0; i < 4; i++)
#pragma unroll
        for (int j = 0; j < 4; j++)
#pragma unroll
            for (int q = 0; q < 4; q++) acc[i][j][q] = 0.f;

    const int niter = K >> 6;
    load_stage(0, 0);
    load_stage(1, 64);

    for (int it = 0; it < niter; it++) {
        if (it + 1 < niter) cp_wait_1(); else cp_wait_all();
        __syncthreads();
        if (it + 2 < niter) load_stage((it + 2) % 3, (it + 2) << 6);

        const uint32_t sA = sb + (it % 3) * GA_STAGE;
        const uint32_t sB = sA + GA_ATILE;

#pragma unroll
        for (int ks = 0; ks < 4; ks++) {
            uint32_t fA[4][4], fB[2][4];
            const uint32_t acol = ks * 32 + (lane >> 4) * 16;
            const uint32_t bcol = ks * 32 + ((lane >> 3) & 1) * 16;
            const uint32_t brow = ((lane >> 4) & 1) * 8 + (lane & 7);
#pragma unroll
            for (int mi = 0; mi < 4; mi++)
                ldm_x4(sA + (wm0 + mi * 16 + (lane & 15)) * GEMM_LDSB + acol, fA[mi]);
#pragma unroll
            for (int np = 0; np < 2; np++)
                ldm_x4(sB + (wn0 + np * 16 + brow) * GEMM_LDSB + bcol, fB[np]);
#pragma unroll
            for (int mi = 0; mi < 4; mi++)
#pragma unroll
                for (int np = 0; np < 2; np++) {
                    mma16816(acc[mi][2 * np],     fA[mi], fB[np]);
                    mma16816(acc[mi][2 * np + 1], fA[mi], fB[np] + 2);
                }
        }
    }
}

// ─────────────────────────────────────────────────────────────────────────────
// GEMM mainloop B: BM=64 (measured best for grid-starved proj_out).
// BN=128, BK=64, 256 thr / 8 warps (2x4), warp tile 32x32, acc[2][4][4].
// ─────────────────────────────────────────────────────────────────────────────
#define GB_ATILE    (64 * GEMM_LDSB)     // 9216
#define GB_BTILE    (128 * GEMM_LDSB)    // 18432
#define GB_STAGE    (GB_ATILE + GB_BTILE)// 27648
#define GB_SMEM     (3 * GB_STAGE)       // 82944

__device__ __forceinline__ void gemm_mainloop_64(
    const __half* __restrict__ pA, int lda,
    const __half* __restrict__ pB, int ldb,
    int K, uint32_t sb, int tid, float acc[2][4][4])
{
    const int w    = tid >> 5;
    const int lane = tid & 31;
    const int wm0 = (w & 1) * 32;
    const int wn0 = (w >> 1) * 32;

    auto load_stage = [&](int st, int k0) {
        const uint32_t s0 = sb + st * GB_STAGE;
        for (int c = tid; c < 512; c += 256) {
            const int r = c >> 3, kc = c & 7;
            cp_async16(s0 + r * GEMM_LDSB + kc * 16, pA + (size_t)r * lda + k0 + kc * 8);
        }
        for (int c = tid; c < 1024; c += 256) {
            const int r = c >> 3, kc = c & 7;
            cp_async16(s0 + GB_ATILE + r * GEMM_LDSB + kc * 16,
                       pB + (size_t)r * ldb + k0 + kc * 8);
        }
        cp_commit();
    };

#pragma unroll
    for (int i = 0; i < 2; i++)
#pragma unroll
        for (int j = 0; j < 4; j++)
#pragma unroll
            for (int q = 0; q < 4; q++) acc[i][j][q] = 0.f;

    const int niter = K >> 6;
    load_stage(0, 0);
    load_stage(1, 64);

    const uint32_t brow = ((lane >> 4) & 1) * 8 + (lane & 7);

    for (int it = 0; it < niter; it++) {
        if (it + 1 < niter) cp_wait_1(); else cp_wait_all();
        __syncthreads();
        if (it + 2 < niter) load_stage((it + 2) % 3, (it + 2) << 6);

        const uint32_t sA = sb + (it % 3) * GB_STAGE;
        const uint32_t sB = sA + GB_ATILE;

#pragma unroll
        for (int ks = 0; ks < 4; ks++) {
            uint32_t fA[2][4], fB[2][4];
            const uint32_t acol = ks * 32 + (lane >> 4) * 16;
            const uint32_t bcol = ks * 32 + ((lane >> 3) & 1) * 16;
#pragma unroll
            for (int mi = 0; mi < 2; mi++)
                ldm_x4(sA + (wm0 + mi * 16 + (lane & 15)) * GEMM_LDSB + acol, fA[mi]);
#pragma unroll
            for (int np = 0; np < 2; np++)
                ldm_x4(sB + (wn0 + np * 16 + brow) * GEMM_LDSB + bcol, fB[np]);
#pragma unroll
            for (int mi = 0; mi < 2; mi++)
#pragma unroll
                for (int np = 0; np < 2; np++) {
                    mma16816(acc[mi][2 * np],     fA[mi], fB[np]);
                    mma16816(acc[mi][2 * np + 1], fA[mi], fB[np] + 2);
                }
        }
    }
}

// ─────────────────────────────────────────────────────────────────────────────
// Batched QKV projection: blockIdx.z selects {Q, K, V}. BM=128 tiles.
// ─────────────────────────────────────────────────────────────────────────────
struct QKVArgs {
    const __half* A[3];
    const __half* W[3];
    const float*  bias[3];
    __half*       C[3];
};

__global__ void __launch_bounds__(256) proj_qkv(QKVArgs args)
{
    extern __shared__ __align__(16) char smem[];
    const uint32_t sb = smem_u32(smem);
    const int tid = threadIdx.x;
    const int z = blockIdx.z;
    const int m0 = blockIdx.x * 128;
    const int n0 = blockIdx.y * 128;

    float acc[4][4][4];
    gemm_mainloop_128(args.A[z] + (size_t)m0 * DD, DD,
                      args.W[z] + (size_t)n0 * DD, DD, DD, sb, tid, acc);

    const float scale = (z == 0) ? QSCALE : 1.f;
    const float* bias = args.bias[z];
    __half* C = args.C[z];

    const int w = tid >> 5, lane = tid & 31;
    const int wm0 = (w & 1) * 64, wn0 = (w >> 1) * 32;
    const int qr = lane >> 2, qc = (lane & 3) * 2;
#pragma unroll
    for (int mi = 0; mi < 4; mi++)
#pragma unroll
        for (int ni = 0; ni < 4; ni++)
#pragma unroll
            for (int h2 = 0; h2 < 2; h2++) {
                const int row = m0 + wm0 + mi * 16 + qr + h2 * 8;
                const int col = n0 + wn0 + ni * 8 + qc;
                const float v0 = (acc[mi][ni][h2 * 2 + 0] + bias[col])     * scale;
                const float v1 = (acc[mi][ni][h2 * 2 + 1] + bias[col + 1]) * scale;
                const int b = row >> 11, s = row & 2047, h = col >> 6, dk = col & 63;
                if (z != 2) {
                    const size_t o = ((((size_t)b * HH + h) * SS) + s) * DK + dk;
                    *(__half2*)&C[o] = __floats2half2_rn(v0, v1);
                } else {
                    const size_t o = ((((size_t)b * HH + h) * DK) + dk) * SS + s;
                    C[o]      = __float2half_rn(v0);
                    C[o + SS] = __float2half_rn(v1);
                }
            }
}

// ─────────────────────────────────────────────────────────────────────────────
// Output projection, split-K=2: out += partial via atomicAdd (out pre-zeroed).
// Exactly two commutative fp32 adds per element -> bitwise deterministic.
// bias folded into the kz=0 partial. BM=64 tiles; grid (MM/64, DD/128, 2).
// ─────────────────────────────────────────────────────────────────────────────
__global__ void __launch_bounds__(256) proj_out_sk(
    const __half* __restrict__ A, const __half* __restrict__ W,
    const float* __restrict__ bias, float* __restrict__ Cf)
{
    extern __shared__ __align__(16) char smem[];
    const uint32_t sb = smem_u32(smem);
    const int tid = threadIdx.x;
    const int m0 = blockIdx.x * 64;
    const int n0 = blockIdx.y * 128;
    const int kz = blockIdx.z;
    const int k0 = kz * (DD / 2);        // 0 or 384

    float acc[2][4][4];
    gemm_mainloop_64(A + (size_t)m0 * DD + k0, DD,
                     W + (size_t)n0 * DD + k0, DD, DD / 2, sb, tid, acc);

    const int w = tid >> 5, lane = tid & 31;
    const int wm0 = (w & 1) * 32, wn0 = (w >> 1) * 32;
    const int qr = lane >> 2, qc = (lane & 3) * 2;
#pragma unroll
    for (int mi = 0; mi < 2; mi++)
#pragma unroll
        for (int ni = 0; ni < 4; ni++)
#pragma unroll
            for (int h2 = 0; h2 < 2; h2++) {
                const int row = m0 + wm0 + mi * 16 + qr + h2 * 8;
                const int col = n0 + wn0 + ni * 8 + qc;
                float v0 = acc[mi][ni][h2 * 2 + 0];
                float v1 = acc[mi][ni][h2 * 2 + 1];
                if (kz == 0) { v0 += bias[col]; v1 += bias[col + 1]; }
                atomicAdd(&Cf[(size_t)row * DD + col],     v0);
                atomicAdd(&Cf[(size_t)row * DD + col + 1], v1);
            }
}

// ─────────────────────────────────────────────────────────────────────────────
// Fused flash attention (unchanged — measured optimum, 4 warps x 32 Q-rows).
// ─────────────────────────────────────────────────────────────────────────────
#define BKV    64
#define LDK    144                       // 64 fp16 = 128B row + 16B pad
#define KPLANE (64 * LDK)                // 9216
#define QPLANE (128 * LDK)               // 18432
#define OFF_Q  0
#define OFF_S  QPLANE                    // 18432
#define STAGEA (2 * KPLANE)              // K + V = 18432
#define FA_SMEM (OFF_S + 3 * STAGEA)     // 73728

__global__ void __launch_bounds__(128, 3) fused_attn()
{
    extern __shared__ __align__(16) char smem[];
    const uint32_t sb = smem_u32(smem);

    const int tid  = threadIdx.x;
    const int w    = tid >> 5;           // 0..3
    const int lane = tid & 31;
    const int qbase = blockIdx.x * 128;
    const int bh   = blockIdx.y;
    const int b    = bh / HH, h = bh % HH;

    const __half* pQ = g_Q  + (size_t)bh * SS * DK;
    const __half* pK = g_K  + (size_t)bh * SS * DK;
    const __half* pV = g_Vt + (size_t)bh * DK * SS;

    auto load_q = [&]() {
        for (int c = tid; c < 1024; c += 128) {
            const int r = c >> 3, kc = c & 7;
            cp_async16(sb + OFF_Q + r * LDK + kc * 16,
                       pQ + (size_t)(qbase + r) * DK + kc * 8);
        }
        cp_commit();
    };
    auto load_kv = [&](int st, int j0) {
        const uint32_t s0 = sb + OFF_S + st * STAGEA;
        for (int c = tid; c < 512; c += 128) {
            const int r = c >> 3, kc = c & 7;
            cp_async16(s0 + r * LDK + kc * 16,
                       pK + (size_t)(j0 + r) * DK + kc * 8);
            cp_async16(s0 + KPLANE + r * LDK + kc * 16,
                       pV + (size_t)r * SS + j0 + kc * 8);
        }
        cp_commit();
    };

    load_q();
    load_kv(0, 0);
    load_kv(1, BKV);

    float Oa[2][8][4];
#pragma unroll
    for (int tt = 0; tt < 2; tt++)
#pragma unroll
        for (int ni = 0; ni < 8; ni++)
#pragma unroll
            for (int q = 0; q < 4; q++) Oa[tt][ni][q] = 0.f;
    float m[2][2] = {{-1e30f, -1e30f}, {-1e30f, -1e30f}};
    float l[2][2] = {{0.f, 0.f}, {0.f, 0.f}};

    const uint32_t ONES[2] = {0x3C003C00u, 0x3C003C00u};   // 1.0h x4

    const uint32_t brow = ((lane >> 4) & 1) * 8 + (lane & 7);
    const uint32_t bcsel = ((lane >> 3) & 1) * 16;
    const uint32_t arow0 = (uint32_t)(w * 32 + (lane & 15)) * LDK;
    const uint32_t arow1 = arow0 + 16 * LDK;
    const uint32_t acsel = (lane >> 4) * 16;

    constexpr int NSTEP = SS / BKV;   // 32
    for (int jt = 0; jt < NSTEP; jt++) {
        if (jt + 1 < NSTEP) cp_wait_1(); else cp_wait_all();
        __syncthreads();
        if (jt + 2 < NSTEP) load_kv((jt + 2) % 3, (jt + 2) * BKV);

        const uint32_t sK = sb + OFF_S + (jt % 3) * STAGEA;
        const uint32_t sV = sK + KPLANE;

        // ---- S' = Qs K^T (log2 units), two m-tiles ----
        float Sa[2][8][4];
#pragma unroll
        for (int tt = 0; tt < 2; tt++)
#pragma unroll
            for (int ni = 0; ni < 8; ni++)
#pragma unroll
                for (int q = 0; q < 4; q++) Sa[tt][ni][q] = 0.f;

#pragma unroll
        for (int ks = 0; ks < 4; ks++) {
            uint32_t Qf0[4], Qf1[4];
            ldm_x4(sb + OFF_Q + arow0 + ks * 32 + acsel, Qf0);
            ldm_x4(sb + OFF_Q + arow1 + ks * 32 + acsel, Qf1);
#pragma unroll
            for (int np = 0; np < 4; np++) {
                uint32_t bf[4];
                ldm_x4(sK + (uint32_t)(np * 16 + brow) * LDK + ks * 32 + bcsel, bf);
                mma16816(Sa[0][2 * np],     Qf0, bf);
                mma16816(Sa[0][2 * np + 1], Qf0, bf + 2);
                mma16816(Sa[1][2 * np],     Qf1, bf);
                mma16816(Sa[1][2 * np + 1], Qf1, bf + 2);
            }
        }

        // ---- online softmax (log2 domain), per m-tile ----
        float mn[2][2], a[2][2];
        bool changed = false;
#pragma unroll
        for (int tt = 0; tt < 2; tt++) {
            float mx0 = -1e30f, mx1 = -1e30f;
#pragma unroll
            for (int ni = 0; ni < 8; ni++) {
                mx0 = fmaxf(mx0, fmaxf(Sa[tt][ni][0], Sa[tt][ni][1]));
                mx1 = fmaxf(mx1, fmaxf(Sa[tt][ni][2], Sa[tt][ni][3]));
            }
            mx0 = fmaxf(mx0, __shfl_xor_sync(0xffffffffu, mx0, 1));
            mx0 = fmaxf(mx0, __shfl_xor_sync(0xffffffffu, mx0, 2));
            mx1 = fmaxf(mx1, __shfl_xor_sync(0xffffffffu, mx1, 1));
            mx1 = fmaxf(mx1, __shfl_xor_sync(0xffffffffu, mx1, 2));
            mn[tt][0] = fmaxf(m[tt][0], mx0);
            mn[tt][1] = fmaxf(m[tt][1], mx1);
            changed |= (mn[tt][0] > m[tt][0]) || (mn[tt][1] > m[tt][1]);
            a[tt][0] = 1.f; a[tt][1] = 1.f;
        }
        if (__any_sync(0xffffffffu, changed)) {
#pragma unroll
            for (int tt = 0; tt < 2; tt++) {
                a[tt][0] = ex2(m[tt][0] - mn[tt][0]);
                a[tt][1] = ex2(m[tt][1] - mn[tt][1]);
#pragma unroll
                for (int ni = 0; ni < 8; ni++) {
                    Oa[tt][ni][0] *= a[tt][0]; Oa[tt][ni][1] *= a[tt][0];
                    Oa[tt][ni][2] *= a[tt][1]; Oa[tt][ni][3] *= a[tt][1];
                }
            }
        }
#pragma unroll
        for (int tt = 0; tt < 2; tt++) { m[tt][0] = mn[tt][0]; m[tt][1] = mn[tt][1]; }

        // ---- pack (S-mn) to half2, half2 exp2 -> fp16 A-fragments ----
        uint32_t pf[2][4][4];
#pragma unroll
        for (int tt = 0; tt < 2; tt++)
#pragma unroll
            for (int t = 0; t < 4; t++) {
                pf[tt][t][0] = h2ex2(pack_h2(Sa[tt][2*t][0]   - mn[tt][0], Sa[tt][2*t][1]   - mn[tt][0]));
                pf[tt][t][1] = h2ex2(pack_h2(Sa[tt][2*t][2]   - mn[tt][1], Sa[tt][2*t][3]   - mn[tt][1]));
                pf[tt][t][2] = h2ex2(pack_h2(Sa[tt][2*t+1][0] - mn[tt][0], Sa[tt][2*t+1][1] - mn[tt][0]));
                pf[tt][t][3] = h2ex2(pack_h2(Sa[tt][2*t+1][2] - mn[tt][1], Sa[tt][2*t+1][3] - mn[tt][1]));
            }

        // ---- l = l*a + P@1 via ones-MMA ----
#pragma unroll
        for (int tt = 0; tt < 2; tt++) {
            float ls[4];
            ls[0] = l[tt][0] * a[tt][0]; ls[1] = 0.f;
            ls[2] = l[tt][1] * a[tt][1]; ls[3] = 0.f;
#pragma unroll
            for (int t = 0; t < 4; t++)
                mma16816(ls, pf[tt][t], ONES);
            l[tt][0] = ls[0]; l[tt][1] = ls[2];
        }

        // ---- O += P V (shared V fragments for both m-tiles) ----
#pragma unroll
        for (int t = 0; t < 4; t++) {
#pragma unroll
            for (int np = 0; np < 4; np++) {
                uint32_t vf[4];
                ldm_x4(sV + (uint32_t)(np * 16 + brow) * LDK + t * 32 + bcsel, vf);
                mma16816(Oa[0][2 * np],     pf[0][t], vf);
                mma16816(Oa[0][2 * np + 1], pf[0][t], vf + 2);
                mma16816(Oa[1][2 * np],     pf[1][t], vf);
                mma16816(Oa[1][2 * np + 1], pf[1][t], vf + 2);
            }
        }
    }

    // ---- epilogue: O /= l, write merged-head fp16 ----
    const int qr = lane >> 2, qc = (lane & 3) * 2;
#pragma unroll
    for (int tt = 0; tt < 2; tt++) {
        const float inv0 = 1.f / l[tt][0], inv1 = 1.f / l[tt][1];
        const int s0r = qbase + w * 32 + tt * 16 + qr;
#pragma unroll
        for (int ni = 0; ni < 8; ni++) {
            const int col = ni * 8 + qc;
            const size_t o0 = ((size_t)(b * SS + s0r))     * DD + h * DK + col;
            const size_t o1 = ((size_t)(b * SS + s0r + 8)) * DD + h * DK + col;
            *(__half2*)&g_O[o0] = __floats2half2_rn(Oa[tt][ni][0] * inv0, Oa[tt][ni][1] * inv0);
            *(__half2*)&g_O[o1] = __floats2half2_rn(Oa[tt][ni][2] * inv1, Oa[tt][ni][3] * inv1);
        }
    }
}

// ─────────────────────────────────────────────────────────────────────────────
// Batched fp32 -> fp16 convert + output zeroing (8 segments via blockIdx.y).
// Segment with s == nullptr writes zeros (8 bytes per index) — initializes
// d_out for the split-K atomicAdd epilogue, no extra launch.
// ─────────────────────────────────────────────────────────────────────────────
struct Cvt8 { const float4* s[8]; __half* d[8]; int n4[8]; };

__global__ void __launch_bounds__(256) cvt16_all(Cvt8 a)
{
    const int t = blockIdx.y;
    const int i = blockIdx.x * 256 + threadIdx.x;
    if (i < a.n4[t]) {
        if (a.s[t]) {
            float4 v = a.s[t][i];
            __half2 x = __floats2half2_rn(v.x, v.y);
            __half2 y = __floats2half2_rn(v.z, v.w);
            *(uint2*)(a.d[t] + 4 * (size_t)i) = make_uint2(*(uint32_t*)&x, *(uint32_t*)&y);
        } else {
            *(uint2*)(a.d[t] + 4 * (size_t)i) = make_uint2(0u, 0u);
        }
    }
}

// ─────────────────────────────────────────────────────────────────────────────
// kernel_launch
// Input order: k, q, v, mask, wq, bq, wk, bk, wv, bv, wo, bo
// ─────────────────────────────────────────────────────────────────────────────
extern "C" void kernel_launch(void* const* d_in, const int* in_sizes, int n_in,
                              void* d_out, int out_size)
{
    const float* k_in = (const float*)d_in[0];
    const float* q_in = (const float*)d_in[1];
    const float* v_in = (const float*)d_in[2];
    const float* wq = (const float*)d_in[4];
    const float* bq = (const float*)d_in[5];
    const float* wk = (const float*)d_in[6];
    const float* bk = (const float*)d_in[7];
    const float* wv = (const float*)d_in[8];
    const float* bv = (const float*)d_in[9];
    const float* wo = (const float*)d_in[10];
    const float* bo = (const float*)d_in[11];
    float* out = (float*)d_out;

    __half *xq, *xk, *xv, *w_q, *w_k, *w_v, *w_o, *Q, *K, *Vt, *O;
    cudaGetSymbolAddress((void**)&xq, g_xq);
    cudaGetSymbolAddress((void**)&xk, g_xk);
    cudaGetSymbolAddress((void**)&xv, g_xv);
    cudaGetSymbolAddress((void**)&w_q, g_wq);
    cudaGetSymbolAddress((void**)&w_k, g_wk);
    cudaGetSymbolAddress((void**)&w_v, g_wv);
    cudaGetSymbolAddress((void**)&w_o, g_wo);
    cudaGetSymbolAddress((void**)&Q,  g_Q);
    cudaGetSymbolAddress((void**)&K,  g_K);
    cudaGetSymbolAddress((void**)&Vt, g_Vt);
    cudaGetSymbolAddress((void**)&O,  g_O);

    cudaFuncSetAttribute(fused_attn,  cudaFuncAttributeMaxDynamicSharedMemorySize, FA_SMEM);
    cudaFuncSetAttribute(proj_qkv,    cudaFuncAttributeMaxDynamicSharedMemorySize, GA_SMEM);
    cudaFuncSetAttribute(proj_out_sk, cudaFuncAttributeMaxDynamicSharedMemorySize, GB_SMEM);

    const int nAct4 = MM * DD / 4;       // 786432 (16B units)
    const int nW4   = DD * DD / 4;       // 147456
    const int nOut8 = MM * DD / 2;       // 1572864 (8B units of fp32 out)

    // 1. fp32 -> fp16 conversions + d_out zeroing (one launch, 8 segments)
    Cvt8 cv;
    cv.s[0] = (const float4*)q_in; cv.d[0] = xq;            cv.n4[0] = nAct4;
    cv.s[1] = (const float4*)k_in; cv.d[1] = xk;            cv.n4[1] = nAct4;
    cv.s[2] = (const float4*)v_in; cv.d[2] = xv;            cv.n4[2] = nAct4;
    cv.s[3] = (const float4*)wq;   cv.d[3] = w_q;           cv.n4[3] = nW4;
    cv.s[4] = (const float4*)wk;   cv.d[4] = w_k;           cv.n4[4] = nW4;
    cv.s[5] = (const float4*)wv;   cv.d[5] = w_v;           cv.n4[5] = nW4;
    cv.s[6] = (const float4*)wo;   cv.d[6] = w_o;           cv.n4[6] = nW4;
    cv.s[7] = nullptr;             cv.d[7] = (__half*)out;  cv.n4[7] = nOut8;
    cvt16_all<<<dim3((nOut8 + 255) / 256, 8), 256>>>(cv);

    // 2. Batched Q/K/V projections (BM=128: 32 x 6 x 3 = 576 CTAs)
    QKVArgs pa;
    pa.A[0] = xq;  pa.A[1] = xk;  pa.A[2] = xv;
    pa.W[0] = w_q; pa.W[1] = w_k; pa.W[2] = w_v;
    pa.bias[0] = bq; pa.bias[1] = bk; pa.bias[2] = bv;
    pa.C[0] = Q; pa.C[1] = K; pa.C[2] = Vt;
    proj_qkv<<<dim3(MM / 128, DD / 128, 3), 256, GA_SMEM>>>(pa);

    // 3. Fused attention (scores + softmax + PV), log2-domain softmax
    fused_attn<<<dim3(SS / 128, BH), 128, FA_SMEM>>>();

    // 4. Output projection, split-K=2 (BM=64: 64 x 6 x 2 = 768 CTAs)
    proj_out_sk<<<dim3(MM / 64, DD / 128, 2), 256, GB_SMEM>>>(O, w_o, bo, out);
}

// round 17
// speedup vs baseline: 1.0977x; 1.0977x over previous
#include <cuda_runtime.h>
#include <cuda_fp16.h>
#include <cstdint>

// ─────────────────────────────────────────────────────────────────────────────
// Dims
// ─────────────────────────────────────────────────────────────────────────────
#define BB 2
#define SS 2048
#define DD 768
#define HH 12
#define DK 64
#define BH 24           // BB*HH
#define MM 4096         // BB*SS

#define QSCALE 0.18033688f   // 0.125 * log2(e)

// ─────────────────────────────────────────────────────────────────────────────
// Scratch (static device globals — no allocation). Single fp16 plane each.
// ─────────────────────────────────────────────────────────────────────────────
__device__ __half g_xq[MM * DD], g_xk[MM * DD], g_xv[MM * DD];
__device__ __half g_wq[DD * DD], g_wk[DD * DD], g_wv[DD * DD], g_wo[DD * DD];
__device__ __half g_Q[BH * SS * DK];     // pre-scaled by 0.125*log2e
__device__ __half g_K[BH * SS * DK];
__device__ __half g_Vt[BH * SS * DK];    // [bh, dk, s]
__device__ __half g_O[MM * DD];          // merged heads [B*S, D]

// ─────────────────────────────────────────────────────────────────────────────
// PTX helpers (baseline ISA only — harness targets sm_103 non-'a', no tcgen05)
// ─────────────────────────────────────────────────────────────────────────────
__device__ __forceinline__ uint32_t smem_u32(const void* p) {
    uint32_t a;
    asm("{ .reg .u64 t; cvta.to.shared.u64 t, %1; cvt.u32.u64 %0, t; }"
        : "=r"(a) : "l"(p));
    return a;
}

__device__ __forceinline__ void cp_async16(uint32_t saddr, const void* gaddr) {
    asm volatile("cp.async.ca.shared.global [%0], [%1], 16;"
                 :: "r"(saddr), "l"(gaddr));
}
__device__ __forceinline__ void cp_commit() {
    asm volatile("cp.async.commit_group;");
}
__device__ __forceinline__ void cp_wait_all() {
    asm volatile("cp.async.wait_group 0;");
}
__device__ __forceinline__ void cp_wait_1() {
    asm volatile("cp.async.wait_group 1;");
}

__device__ __forceinline__ void ldm_x4(uint32_t addr, uint32_t* r) {
    asm volatile("ldmatrix.sync.aligned.m8n8.x4.shared.b16 {%0,%1,%2,%3}, [%4];"
                 : "=r"(r[0]), "=r"(r[1]), "=r"(r[2]), "=r"(r[3]) : "r"(addr));
}

// fp16 in, fp32 accumulate
__device__ __forceinline__ void mma16816(float* c, const uint32_t* a, const uint32_t* b) {
    asm volatile(
        "mma.sync.aligned.m16n8k16.row.col.f32.f16.f16.f32 "
        "{%0,%1,%2,%3}, {%4,%5,%6,%7}, {%8,%9}, {%0,%1,%2,%3};"
        : "+f"(c[0]), "+f"(c[1]), "+f"(c[2]), "+f"(c[3])
        : "r"(a[0]), "r"(a[1]), "r"(a[2]), "r"(a[3]), "r"(b[0]), "r"(b[1]));
}

__device__ __forceinline__ uint32_t pack_h2(float a, float b) {
    __half2 t = __floats2half2_rn(a, b);   // a in low half
    return *(uint32_t*)&t;
}

__device__ __forceinline__ float ex2(float x) {
    float y;
    asm("ex2.approx.f32 %0, %1;" : "=f"(y) : "f"(x));
    return y;
}

// half2 exp2 — one MUFU for two values
__device__ __forceinline__ uint32_t h2ex2(uint32_t x) {
    uint32_t y;
    asm("ex2.approx.f16x2 %0, %1;" : "=r"(y) : "r"(x));
    return y;
}

// ─────────────────────────────────────────────────────────────────────────────
// GEMM mainloop A: BM=128 (measured best for proj_qkv, ~2 perfect waves).
// BN=128, BK=64, 256 thr / 8 warps (2x4), warp tile 64x32, acc[4][4][4].
// 3-stage cp.async ring.
// ─────────────────────────────────────────────────────────────────────────────
#define GEMM_LDSB   144                  // 64 fp16 = 128B + 16B pad
#define GA_ATILE    (128 * GEMM_LDSB)    // 18432
#define GA_STAGE    (2 * GA_ATILE)       // 36864
#define GA_SMEM     (3 * GA_STAGE)       // 110592

__device__ __forceinline__ void gemm_mainloop_128(
    const __half* __restrict__ pA, int lda,
    const __half* __restrict__ pB, int ldb,
    int K, uint32_t sb, int tid, float acc[4][4][4])
{
    const int w    = tid >> 5;
    const int lane = tid & 31;
    const int wm0 = (w & 1) * 64;
    const int wn0 = (w >> 1) * 32;

    auto load_stage = [&](int st, int k0) {
        const uint32_t s0 = sb + st * GA_STAGE;
        for (int c = tid; c < 1024; c += 256) {     // 128 rows x 8 chunks, A and B
            const int r = c >> 3, kc = c & 7;
            cp_async16(s0 + r * GEMM_LDSB + kc * 16, pA + (size_t)r * lda + k0 + kc * 8);
            cp_async16(s0 + GA_ATILE + r * GEMM_LDSB + kc * 16,
                       pB + (size_t)r * ldb + k0 + kc * 8);
        }
        cp_commit();
    };

#pragma unroll
    for (int i = 0; i < 4; i++)
#pragma unroll
        for (int j = 0; j < 4; j++)
#pragma unroll
            for (int q = 0; q < 4; q++) acc[i][j][q] = 0.f;

    const int niter = K >> 6;   // 12
    load_stage(0, 0);
    load_stage(1, 64);

    for (int it = 0; it < niter; it++) {
        if (it + 1 < niter) cp_wait_1(); else cp_wait_all();
        __syncthreads();
        if (it + 2 < niter) load_stage((it + 2) % 3, (it + 2) << 6);

        const uint32_t sA = sb + (it % 3) * GA_STAGE;
        const uint32_t sB = sA + GA_ATILE;

#pragma unroll
        for (int ks = 0; ks < 4; ks++) {
            uint32_t fA[4][4], fB[2][4];
            const uint32_t acol = ks * 32 + (lane >> 4) * 16;
            const uint32_t bcol = ks * 32 + ((lane >> 3) & 1) * 16;
            const uint32_t brow = ((lane >> 4) & 1) * 8 + (lane & 7);
#pragma unroll
            for (int mi = 0; mi < 4; mi++)
                ldm_x4(sA + (wm0 + mi * 16 + (lane & 15)) * GEMM_LDSB + acol, fA[mi]);
#pragma unroll
            for (int np = 0; np < 2; np++)
                ldm_x4(sB + (wn0 + np * 16 + brow) * GEMM_LDSB + bcol, fB[np]);
#pragma unroll
            for (int mi = 0; mi < 4; mi++)
#pragma unroll
                for (int np = 0; np < 2; np++) {
                    mma16816(acc[mi][2 * np],     fA[mi], fB[np]);
                    mma16816(acc[mi][2 * np + 1], fA[mi], fB[np] + 2);
                }
        }
    }
}

// ─────────────────────────────────────────────────────────────────────────────
// GEMM mainloop B: BM=64 (measured best for grid-starved proj_out).
// Round 17: 2-stage ring (smem 55.3 KB -> up to 4 CTAs/SM; all 384 CTAs
// resident in a single wave). Race-free order: wait_all -> sync -> load next
// -> compute (next load targets the buffer computed LAST iter, all threads
// past the sync).
// ─────────────────────────────────────────────────────────────────────────────
#define GB_ATILE    (64 * GEMM_LDSB)     // 9216
#define GB_BTILE    (128 * GEMM_LDSB)    // 18432
#define GB_STAGE    (GB_ATILE + GB_BTILE)// 27648
#define GB_SMEM     (2 * GB_STAGE)       // 55296

__device__ __forceinline__ void gemm_mainloop_64(
    const __half* __restrict__ pA, int lda,
    const __half* __restrict__ pB, int ldb,
    int K, uint32_t sb, int tid, float acc[2][4][4])
{
    const int w    = tid >> 5;
    const int lane = tid & 31;
    const int wm0 = (w & 1) * 32;
    const int wn0 = (w >> 1) * 32;

    auto load_stage = [&](int st, int k0) {
        const uint32_t s0 = sb + st * GB_STAGE;
        for (int c = tid; c < 512; c += 256) {
            const int r = c >> 3, kc = c & 7;
            cp_async16(s0 + r * GEMM_LDSB + kc * 16, pA + (size_t)r * lda + k0 + kc * 8);
        }
        for (int c = tid; c < 1024; c += 256) {
            const int r = c >> 3, kc = c & 7;
            cp_async16(s0 + GB_ATILE + r * GEMM_LDSB + kc * 16,
                       pB + (size_t)r * ldb + k0 + kc * 8);
        }
        cp_commit();
    };

#pragma unroll
    for (int i = 0; i < 2; i++)
#pragma unroll
        for (int j = 0; j < 4; j++)
#pragma unroll
            for (int q = 0; q < 4; q++) acc[i][j][q] = 0.f;

    const int niter = K >> 6;   // 12
    load_stage(0, 0);

    const uint32_t brow = ((lane >> 4) & 1) * 8 + (lane & 7);

    for (int it = 0; it < niter; it++) {
        cp_wait_all();               // stage `it` complete (it+1 not yet issued)
        __syncthreads();             // everyone done with buffer (it+1)&1 from it-1
        if (it + 1 < niter) load_stage((it + 1) & 1, (it + 1) << 6);

        const uint32_t sA = sb + (it & 1) * GB_STAGE;
        const uint32_t sB = sA + GB_ATILE;

#pragma unroll
        for (int ks = 0; ks < 4; ks++) {
            uint32_t fA[2][4], fB[2][4];
            const uint32_t acol = ks * 32 + (lane >> 4) * 16;
            const uint32_t bcol = ks * 32 + ((lane >> 3) & 1) * 16;
#pragma unroll
            for (int mi = 0; mi < 2; mi++)
                ldm_x4(sA + (wm0 + mi * 16 + (lane & 15)) * GEMM_LDSB + acol, fA[mi]);
#pragma unroll
            for (int np = 0; np < 2; np++)
                ldm_x4(sB + (wn0 + np * 16 + brow) * GEMM_LDSB + bcol, fB[np]);
#pragma unroll
            for (int mi = 0; mi < 2; mi++)
#pragma unroll
                for (int np = 0; np < 2; np++) {
                    mma16816(acc[mi][2 * np],     fA[mi], fB[np]);
                    mma16816(acc[mi][2 * np + 1], fA[mi], fB[np] + 2);
                }
        }
    }
}

// ─────────────────────────────────────────────────────────────────────────────
// Batched QKV projection: blockIdx.z selects {Q, K, V}. BM=128 tiles.
// ─────────────────────────────────────────────────────────────────────────────
struct QKVArgs {
    const __half* A[3];
    const __half* W[3];
    const float*  bias[3];
    __half*       C[3];
};

__global__ void __launch_bounds__(256) proj_qkv(QKVArgs args)
{
    extern __shared__ __align__(16) char smem[];
    const uint32_t sb = smem_u32(smem);
    const int tid = threadIdx.x;
    const int z = blockIdx.z;
    const int m0 = blockIdx.x * 128;
    const int n0 = blockIdx.y * 128;

    float acc[4][4][4];
    gemm_mainloop_128(args.A[z] + (size_t)m0 * DD, DD,
                      args.W[z] + (size_t)n0 * DD, DD, DD, sb, tid, acc);

    const float scale = (z == 0) ? QSCALE : 1.f;
    const float* bias = args.bias[z];
    __half* C = args.C[z];

    const int w = tid >> 5, lane = tid & 31;
    const int wm0 = (w & 1) * 64, wn0 = (w >> 1) * 32;
    const int qr = lane >> 2, qc = (lane & 3) * 2;
#pragma unroll
    for (int mi = 0; mi < 4; mi++)
#pragma unroll
        for (int ni = 0; ni < 4; ni++)
#pragma unroll
            for (int h2 = 0; h2 < 2; h2++) {
                const int row = m0 + wm0 + mi * 16 + qr + h2 * 8;
                const int col = n0 + wn0 + ni * 8 + qc;
                const float v0 = (acc[mi][ni][h2 * 2 + 0] + bias[col])     * scale;
                const float v1 = (acc[mi][ni][h2 * 2 + 1] + bias[col + 1]) * scale;
                const int b = row >> 11, s = row & 2047, h = col >> 6, dk = col & 63;
                if (z != 2) {
                    const size_t o = ((((size_t)b * HH + h) * SS) + s) * DK + dk;
                    *(__half2*)&C[o] = __floats2half2_rn(v0, v1);
                } else {
                    const size_t o = ((((size_t)b * HH + h) * DK) + dk) * SS + s;
                    C[o]      = __float2half_rn(v0);
                    C[o + SS] = __float2half_rn(v1);
                }
            }
}

// ─────────────────────────────────────────────────────────────────────────────
// Output projection: out = O @ Wo^T + bo, fp32 output. BM=64 tiles, 2-stage.
// ─────────────────────────────────────────────────────────────────────────────
__global__ void __launch_bounds__(256) proj_out(
    const __half* __restrict__ A, const __half* __restrict__ W,
    const float* __restrict__ bias, float* __restrict__ Cf)
{
    extern __shared__ __align__(16) char smem[];
    const uint32_t sb = smem_u32(smem);
    const int tid = threadIdx.x;
    const int m0 = blockIdx.x * 64;
    const int n0 = blockIdx.y * 128;

    float acc[2][4][4];
    gemm_mainloop_64(A + (size_t)m0 * DD, DD, W + (size_t)n0 * DD, DD, DD, sb, tid, acc);

    const int w = tid >> 5, lane = tid & 31;
    const int wm0 = (w & 1) * 32, wn0 = (w >> 1) * 32;
    const int qr = lane >> 2, qc = (lane & 3) * 2;
#pragma unroll
    for (int mi = 0; mi < 2; mi++)
#pragma unroll
        for (int ni = 0; ni < 4; ni++)
#pragma unroll
            for (int h2 = 0; h2 < 2; h2++) {
                const int row = m0 + wm0 + mi * 16 + qr + h2 * 8;
                const int col = n0 + wn0 + ni * 8 + qc;
                *(float2*)&Cf[(size_t)row * DD + col] =
                    make_float2(acc[mi][ni][h2 * 2 + 0] + bias[col],
                                acc[mi][ni][h2 * 2 + 1] + bias[col + 1]);
            }
}

// ─────────────────────────────────────────────────────────────────────────────
// Fused flash attention (unchanged — measured optimum, 4 warps x 32 Q-rows).
// ─────────────────────────────────────────────────────────────────────────────
#define BKV    64
#define LDK    144                       // 64 fp16 = 128B row + 16B pad
#define KPLANE (64 * LDK)                // 9216
#define QPLANE (128 * LDK)               // 18432
#define OFF_Q  0
#define OFF_S  QPLANE                    // 18432
#define STAGEA (2 * KPLANE)              // K + V = 18432
#define FA_SMEM (OFF_S + 3 * STAGEA)     // 73728

__global__ void __launch_bounds__(128, 3) fused_attn()
{
    extern __shared__ __align__(16) char smem[];
    const uint32_t sb = smem_u32(smem);

    const int tid  = threadIdx.x;
    const int w    = tid >> 5;           // 0..3
    const int lane = tid & 31;
    const int qbase = blockIdx.x * 128;
    const int bh   = blockIdx.y;
    const int b    = bh / HH, h = bh % HH;

    const __half* pQ = g_Q  + (size_t)bh * SS * DK;
    const __half* pK = g_K  + (size_t)bh * SS * DK;
    const __half* pV = g_Vt + (size_t)bh * DK * SS;

    auto load_q = [&]() {
        for (int c = tid; c < 1024; c += 128) {
            const int r = c >> 3, kc = c & 7;
            cp_async16(sb + OFF_Q + r * LDK + kc * 16,
                       pQ + (size_t)(qbase + r) * DK + kc * 8);
        }
        cp_commit();
    };
    auto load_kv = [&](int st, int j0) {
        const uint32_t s0 = sb + OFF_S + st * STAGEA;
        for (int c = tid; c < 512; c += 128) {
            const int r = c >> 3, kc = c & 7;
            cp_async16(s0 + r * LDK + kc * 16,
                       pK + (size_t)(j0 + r) * DK + kc * 8);
            cp_async16(s0 + KPLANE + r * LDK + kc * 16,
                       pV + (size_t)r * SS + j0 + kc * 8);
        }
        cp_commit();
    };

    load_q();
    load_kv(0, 0);
    load_kv(1, BKV);

    float Oa[2][8][4];
#pragma unroll
    for (int tt = 0; tt < 2; tt++)
#pragma unroll
        for (int ni = 0; ni < 8; ni++)
#pragma unroll
            for (int q = 0; q < 4; q++) Oa[tt][ni][q] = 0.f;
    float m[2][2] = {{-1e30f, -1e30f}, {-1e30f, -1e30f}};
    float l[2][2] = {{0.f, 0.f}, {0.f, 0.f}};

    const uint32_t ONES[2] = {0x3C003C00u, 0x3C003C00u};   // 1.0h x4

    const uint32_t brow = ((lane >> 4) & 1) * 8 + (lane & 7);
    const uint32_t bcsel = ((lane >> 3) & 1) * 16;
    const uint32_t arow0 = (uint32_t)(w * 32 + (lane & 15)) * LDK;
    const uint32_t arow1 = arow0 + 16 * LDK;
    const uint32_t acsel = (lane >> 4) * 16;

    constexpr int NSTEP = SS / BKV;   // 32
    for (int jt = 0; jt < NSTEP; jt++) {
        if (jt + 1 < NSTEP) cp_wait_1(); else cp_wait_all();
        __syncthreads();
        if (jt + 2 < NSTEP) load_kv((jt + 2) % 3, (jt + 2) * BKV);

        const uint32_t sK = sb + OFF_S + (jt % 3) * STAGEA;
        const uint32_t sV = sK + KPLANE;

        // ---- S' = Qs K^T (log2 units), two m-tiles ----
        float Sa[2][8][4];
#pragma unroll
        for (int tt = 0; tt < 2; tt++)
#pragma unroll
            for (int ni = 0; ni < 8; ni++)
#pragma unroll
                for (int q = 0; q < 4; q++) Sa[tt][ni][q] = 0.f;

#pragma unroll
        for (int ks = 0; ks < 4; ks++) {
            uint32_t Qf0[4], Qf1[4];
            ldm_x4(sb + OFF_Q + arow0 + ks * 32 + acsel, Qf0);
            ldm_x4(sb + OFF_Q + arow1 + ks * 32 + acsel, Qf1);
#pragma unroll
            for (int np = 0; np < 4; np++) {
                uint32_t bf[4];
                ldm_x4(sK + (uint32_t)(np * 16 + brow) * LDK + ks * 32 + bcsel, bf);
                mma16816(Sa[0][2 * np],     Qf0, bf);
                mma16816(Sa[0][2 * np + 1], Qf0, bf + 2);
                mma16816(Sa[1][2 * np],     Qf1, bf);
                mma16816(Sa[1][2 * np + 1], Qf1, bf + 2);
            }
        }

        // ---- online softmax (log2 domain), per m-tile ----
        float mn[2][2], a[2][2];
        bool changed = false;
#pragma unroll
        for (int tt = 0; tt < 2; tt++) {
            float mx0 = -1e30f, mx1 = -1e30f;
#pragma unroll
            for (int ni = 0; ni < 8; ni++) {
                mx0 = fmaxf(mx0, fmaxf(Sa[tt][ni][0], Sa[tt][ni][1]));
                mx1 = fmaxf(mx1, fmaxf(Sa[tt][ni][2], Sa[tt][ni][3]));
            }
            mx0 = fmaxf(mx0, __shfl_xor_sync(0xffffffffu, mx0, 1));
            mx0 = fmaxf(mx0, __shfl_xor_sync(0xffffffffu, mx0, 2));
            mx1 = fmaxf(mx1, __shfl_xor_sync(0xffffffffu, mx1, 1));
            mx1 = fmaxf(mx1, __shfl_xor_sync(0xffffffffu, mx1, 2));
            mn[tt][0] = fmaxf(m[tt][0], mx0);
            mn[tt][1] = fmaxf(m[tt][1], mx1);
            changed |= (mn[tt][0] > m[tt][0]) || (mn[tt][1] > m[tt][1]);
            a[tt][0] = 1.f; a[tt][1] = 1.f;
        }
        if (__any_sync(0xffffffffu, changed)) {
#pragma unroll
            for (int tt = 0; tt < 2; tt++) {
                a[tt][0] = ex2(m[tt][0] - mn[tt][0]);
                a[tt][1] = ex2(m[tt][1] - mn[tt][1]);
#pragma unroll
                for (int ni = 0; ni < 8; ni++) {
                    Oa[tt][ni][0] *= a[tt][0]; Oa[tt][ni][1] *= a[tt][0];
                    Oa[tt][ni][2] *= a[tt][1]; Oa[tt][ni][3] *= a[tt][1];
                }
            }
        }
#pragma unroll
        for (int tt = 0; tt < 2; tt++) { m[tt][0] = mn[tt][0]; m[tt][1] = mn[tt][1]; }

        // ---- pack (S-mn) to half2, half2 exp2 -> fp16 A-fragments ----
        uint32_t pf[2][4][4];
#pragma unroll
        for (int tt = 0; tt < 2; tt++)
#pragma unroll
            for (int t = 0; t < 4; t++) {
                pf[tt][t][0] = h2ex2(pack_h2(Sa[tt][2*t][0]   - mn[tt][0], Sa[tt][2*t][1]   - mn[tt][0]));
                pf[tt][t][1] = h2ex2(pack_h2(Sa[tt][2*t][2]   - mn[tt][1], Sa[tt][2*t][3]   - mn[tt][1]));
                pf[tt][t][2] = h2ex2(pack_h2(Sa[tt][2*t+1][0] - mn[tt][0], Sa[tt][2*t+1][1] - mn[tt][0]));
                pf[tt][t][3] = h2ex2(pack_h2(Sa[tt][2*t+1][2] - mn[tt][1], Sa[tt][2*t+1][3] - mn[tt][1]));
            }

        // ---- l = l*a + P@1 via ones-MMA ----
#pragma unroll
        for (int tt = 0; tt < 2; tt++) {
            float ls[4];
            ls[0] = l[tt][0] * a[tt][0]; ls[1] = 0.f;
            ls[2] = l[tt][1] * a[tt][1]; ls[3] = 0.f;
#pragma unroll
            for (int t = 0; t < 4; t++)
                mma16816(ls, pf[tt][t], ONES);
            l[tt][0] = ls[0]; l[tt][1] = ls[2];
        }

        // ---- O += P V (shared V fragments for both m-tiles) ----
#pragma unroll
        for (int t = 0; t < 4; t++) {
#pragma unroll
            for (int np = 0; np < 4; np++) {
                uint32_t vf[4];
                ldm_x4(sV + (uint32_t)(np * 16 + brow) * LDK + t * 32 + bcsel, vf);
                mma16816(Oa[0][2 * np],     pf[0][t], vf);
                mma16816(Oa[0][2 * np + 1], pf[0][t], vf + 2);
                mma16816(Oa[1][2 * np],     pf[1][t], vf);
                mma16816(Oa[1][2 * np + 1], pf[1][t], vf + 2);
            }
        }
    }

    // ---- epilogue: O /= l, write merged-head fp16 ----
    const int qr = lane >> 2, qc = (lane & 3) * 2;
#pragma unroll
    for (int tt = 0; tt < 2; tt++) {
        const float inv0 = 1.f / l[tt][0], inv1 = 1.f / l[tt][1];
        const int s0r = qbase + w * 32 + tt * 16 + qr;
#pragma unroll
        for (int ni = 0; ni < 8; ni++) {
            const int col = ni * 8 + qc;
            const size_t o0 = ((size_t)(b * SS + s0r))     * DD + h * DK + col;
            const size_t o1 = ((size_t)(b * SS + s0r + 8)) * DD + h * DK + col;
            *(__half2*)&g_O[o0] = __floats2half2_rn(Oa[tt][ni][0] * inv0, Oa[tt][ni][1] * inv0);
            *(__half2*)&g_O[o1] = __floats2half2_rn(Oa[tt][ni][2] * inv1, Oa[tt][ni][3] * inv1);
        }
    }
}

// ─────────────────────────────────────────────────────────────────────────────
// Single batched fp32 -> fp16 convert (7 segments via blockIdx.y)
// ─────────────────────────────────────────────────────────────────────────────
struct Cvt7 { const float4* s[7]; __half* d[7]; int n4[7]; };

__global__ void __launch_bounds__(256) cvt16_all(Cvt7 a)
{
    const int t = blockIdx.y;
    const int i = blockIdx.x * 256 + threadIdx.x;
    if (i < a.n4[t]) {
        float4 v = a.s[t][i];
        __half2 x = __floats2half2_rn(v.x, v.y);
        __half2 y = __floats2half2_rn(v.z, v.w);
        *(uint2*)(a.d[t] + 4 * (size_t)i) = make_uint2(*(uint32_t*)&x, *(uint32_t*)&y);
    }
}

// ─────────────────────────────────────────────────────────────────────────────
// kernel_launch
// Input order: k, q, v, mask, wq, bq, wk, bk, wv, bv, wo, bo
// ─────────────────────────────────────────────────────────────────────────────
extern "C" void kernel_launch(void* const* d_in, const int* in_sizes, int n_in,
                              void* d_out, int out_size)
{
    const float* k_in = (const float*)d_in[0];
    const float* q_in = (const float*)d_in[1];
    const float* v_in = (const float*)d_in[2];
    const float* wq = (const float*)d_in[4];
    const float* bq = (const float*)d_in[5];
    const float* wk = (const float*)d_in[6];
    const float* bk = (const float*)d_in[7];
    const float* wv = (const float*)d_in[8];
    const float* bv = (const float*)d_in[9];
    const float* wo = (const float*)d_in[10];
    const float* bo = (const float*)d_in[11];
    float* out = (float*)d_out;

    __half *xq, *xk, *xv, *w_q, *w_k, *w_v, *w_o, *Q, *K, *Vt, *O;
    cudaGetSymbolAddress((void**)&xq, g_xq);
    cudaGetSymbolAddress((void**)&xk, g_xk);
    cudaGetSymbolAddress((void**)&xv, g_xv);
    cudaGetSymbolAddress((void**)&w_q, g_wq);
    cudaGetSymbolAddress((void**)&w_k, g_wk);
    cudaGetSymbolAddress((void**)&w_v, g_wv);
    cudaGetSymbolAddress((void**)&w_o, g_wo);
    cudaGetSymbolAddress((void**)&Q,  g_Q);
    cudaGetSymbolAddress((void**)&K,  g_K);
    cudaGetSymbolAddress((void**)&Vt, g_Vt);
    cudaGetSymbolAddress((void**)&O,  g_O);

    cudaFuncSetAttribute(fused_attn, cudaFuncAttributeMaxDynamicSharedMemorySize, FA_SMEM);
    cudaFuncSetAttribute(proj_qkv,   cudaFuncAttributeMaxDynamicSharedMemorySize, GA_SMEM);
    cudaFuncSetAttribute(proj_out,   cudaFuncAttributeMaxDynamicSharedMemorySize, GB_SMEM);

    const int nAct4 = MM * DD / 4, nW4 = DD * DD / 4;

    // 1. fp32 -> fp16 conversions (one launch, 7 segments)
    Cvt7 cv;
    cv.s[0] = (const float4*)q_in; cv.d[0] = xq;  cv.n4[0] = nAct4;
    cv.s[1] = (const float4*)k_in; cv.d[1] = xk;  cv.n4[1] = nAct4;
    cv.s[2] = (const float4*)v_in; cv.d[2] = xv;  cv.n4[2] = nAct4;
    cv.s[3] = (const float4*)wq;   cv.d[3] = w_q; cv.n4[3] = nW4;
    cv.s[4] = (const float4*)wk;   cv.d[4] = w_k; cv.n4[4] = nW4;
    cv.s[5] = (const float4*)wv;   cv.d[5] = w_v; cv.n4[5] = nW4;
    cv.s[6] = (const float4*)wo;   cv.d[6] = w_o; cv.n4[6] = nW4;
    cvt16_all<<<dim3((nAct4 + 255) / 256, 7), 256>>>(cv);

    // 2. Batched Q/K/V projections (BM=128: 32 x 6 x 3 = 576 CTAs)
    QKVArgs pa;
    pa.A[0] = xq;  pa.A[1] = xk;  pa.A[2] = xv;
    pa.W[0] = w_q; pa.W[1] = w_k; pa.W[2] = w_v;
    pa.bias[0] = bq; pa.bias[1] = bk; pa.bias[2] = bv;
    pa.C[0] = Q; pa.C[1] = K; pa.C[2] = Vt;
    proj_qkv<<<dim3(MM / 128, DD / 128, 3), 256, GA_SMEM>>>(pa);

    // 3. Fused attention (scores + softmax + PV), log2-domain softmax
    fused_attn<<<dim3(SS / 128, BH), 128, FA_SMEM>>>();

    // 4. Output projection into d_out (BM=64, 2-stage: 64 x 6 = 384 CTAs, 1 wave)
    proj_out<<<dim3(MM / 64, DD / 128), 256, GB_SMEM>>>(O, w_o, bo, out);
}